// round 15
// baseline (speedup 1.0000x reference)
#include <cuda_runtime.h>
#include <cuda_fp16.h>
#include <cstdint>

#define B_ 256
#define N_ 192
#define D_ 512
#define E_ 1024
#define H_ 512
#define K_ 58
#define M_ (B_*K_)        // 14848 real rows
#define MP_ (B_*64)       // 16384 padded rows (64 per batch, rows k>=58 stay zero)

// ---------------- scratch (static device globals; zero-init, no allocation) --
__device__ __half g_X[(size_t)MP_*1024];    // [MP,1024]: 0:512 base, 512:1024 bn(relu(h)); pad rows 0
__device__ __half g_hpre[(size_t)MP_*H_];   // [MP,512] fp16 pre-BN hidden
__device__ __half g_W1h[H_*D_];             // fp16 W1
__device__ __half g_Wcat[E_*1024];          // fp16 [W_fc | W2]
__device__ float  g_bias2[E_];              // b_fc + b2
__device__ float  g_stats[2*H_];            // col sums / sumsq

// ---------------- fused topk + gather + prep (one launch, no deps) ------------
// blocks [0, B_*N_): block (b,p) ranks patch p in batch b (exact lax.top_k set
//   semantics, tie-break lower index); if rank<K, gathers+L2-normalizes the
//   patch embedding into padded X slot (b*64+rank). Deterministic, no atomics.
// blocks [B_*N_, +8192): weight casts + bias fuse + stat zeroing.
__global__ void gather_topk_kernel(const float* __restrict__ emb,
                                   const float* __restrict__ am,
                                   const float* __restrict__ Wfc, const float* __restrict__ bfc,
                                   const float* __restrict__ W1,  const float* __restrict__ W2,
                                   const float* __restrict__ b2)
{
    int bid = blockIdx.x;
    int t = threadIdx.x;
    if (bid < B_*N_) {
        int b = bid / N_;
        int p = bid - b*N_;
        __shared__ float sv[N_];
        __shared__ float sm[4];
        __shared__ int sr;
        // load attention row am[b,0,1:193]
        for (int i = t; i < N_; i += 128)
            sv[i] = am[(size_t)b*((N_+1)*(N_+1)) + 1 + i];
        __syncthreads();
        float my = sv[p];
        // rank(p): count entries strictly better (ties -> lower index wins)
        int cnt = 0;
        for (int i = t; i < N_; i += 128) {
            float v = sv[i];
            cnt += (v > my) || (v == my && i < p);
        }
        #pragma unroll
        for (int o = 16; o; o >>= 1) cnt += __shfl_xor_sync(0xffffffffu, cnt, o);
        if ((t & 31) == 0) sm[t >> 5] = (float)cnt;
        __syncthreads();
        if (t == 0) sr = (int)(sm[0] + sm[1] + sm[2] + sm[3]);
        __syncthreads();
        int r = sr;
        if (r >= K_) return;
        // gather + L2 normalize + fp16 into padded slot
        const float4* src = (const float4*)(emb + (size_t)(b*N_ + p)*D_);
        float4 v = src[t];
        float s = v.x*v.x + v.y*v.y + v.z*v.z + v.w*v.w;
        #pragma unroll
        for (int o = 16; o; o >>= 1) s += __shfl_xor_sync(0xffffffffu, s, o);
        __syncthreads();
        if ((t & 31) == 0) sm[t >> 5] = s;
        __syncthreads();
        float nrm = sqrtf(sm[0] + sm[1] + sm[2] + sm[3]) + 1e-8f;
        size_t row = (size_t)(b*64 + r);
        __half2* dst = (__half2*)(g_X + row*1024 + t*4);
        dst[0] = __floats2half2_rn(v.x/nrm, v.y/nrm);
        dst[1] = __floats2half2_rn(v.z/nrm, v.w/nrm);
    } else {
        int i = (bid - B_*N_)*128 + t;     // 0..1048575
        {
            int e = i >> 10, c = i & 1023;
            float v = (c < 512) ? Wfc[e*512 + c] : W2[e*512 + (c - 512)];
            g_Wcat[i] = __float2half_rn(v);
        }
        if (i < H_*D_) g_W1h[i] = __float2half_rn(W1[i]);
        if (i < E_)    g_bias2[i] = bfc[i] + b2[i];
        if (i < 2*H_)  g_stats[i] = 0.f;
    }
}

// ---------------- fp16 tensor-core GEMM: C = A @ B^T + bias -------------------
// BM=128, BN=128; 128 threads = 4 warps (2x2), warp tile 64x64.
// GEMM1: BKt=32, STGt=4, MINB=3 -> 64KB smem, 3 CTAs/SM.
// GEMM2: BKt=64, STGt=3, MINB=2 -> 96KB smem, 2 CTAs/SM (R7 optimum).
#define BMt 128
#define BN 128

__device__ __forceinline__ void cp16(uint32_t dst, const void* src) {
    asm volatile("cp.async.cg.shared.global [%0], [%1], 16;\n" :: "r"(dst), "l"(src));
}
__device__ __forceinline__ uint32_t smem_u32(const void* p) {
    uint32_t a;
    asm("{ .reg .u64 t; cvta.to.shared.u64 t, %1; cvt.u32.u64 %0, t; }" : "=r"(a) : "l"(p));
    return a;
}

template<bool FSTAT, int BKt, int STGt, int MINB>
__global__ __launch_bounds__(128, MINB)
void gemm_tc(const __half* __restrict__ A, int lda,
             const __half* __restrict__ Bm, int ldb,
             __half* __restrict__ Ch, int ldc,
             const float* __restrict__ bias, int Kdim,
             float* __restrict__ stats, float* __restrict__ omax)
{
    constexpr int STAGE_BYTES = (BMt + BN)*BKt*2;
    constexpr int A_BYTES     = BMt*BKt*2;
    constexpr int ROWB        = BKt*2;
    constexpr int CPR         = BKt/8;
    constexpr int RSTEP       = 128/CPR;
    constexpr int KS          = BKt/16;

    extern __shared__ __half sh[];
    const int tid  = threadIdx.x;
    const int lane = tid & 31, wid = tid >> 5;
    const int wm = wid >> 1, wn = wid & 1;
    const int m0 = blockIdx.y*BMt, n0 = blockIdx.x*BN;

    uint32_t sbase = smem_u32(sh);

    auto swz = [](int c, int r) -> int {
        return (BKt == 64) ? (c ^ (r & 7)) : (c ^ ((r >> 1) & 3));
    };

    float acc[4][8][4];
    #pragma unroll
    for (int i = 0; i < 4; ++i)
        #pragma unroll
        for (int j = 0; j < 8; ++j)
            #pragma unroll
            for (int k = 0; k < 4; ++k) acc[i][j][k] = 0.f;

    const int cr = tid / CPR;
    const int cc = tid % CPR;
    const __half* Ag[CPR]; uint32_t oA[CPR];
    #pragma unroll
    for (int i = 0; i < CPR; ++i) {
        int r = cr + i*RSTEP;
        Ag[i] = A + (size_t)(m0 + r)*lda + cc*8;
        oA[i] = r*ROWB + swz(cc, r)*16;
    }
    const __half* Bg[CPR]; uint32_t oB[CPR];
    #pragma unroll
    for (int i = 0; i < CPR; ++i) {
        int r = cr + i*RSTEP;
        Bg[i] = Bm + (size_t)(n0 + r)*ldb + cc*8;
        oB[i] = A_BYTES + r*ROWB + swz(cc, r)*16;
    }

    const int mi  = lane >> 3;
    const int lr8 = lane & 7;
    int arow[4];
    #pragma unroll
    for (int mt = 0; mt < 4; ++mt) arow[mt] = wm*64 + mt*16 + ((mi & 1) << 3) + lr8;
    const int akadd = mi >> 1;
    int brow[4];
    #pragma unroll
    for (int p = 0; p < 4; ++p) brow[p] = wn*64 + ((2*p + (mi >> 1)) << 3) + lr8;
    const int bkadd = mi & 1;

    auto issue = [&](int kt, int st) {
        uint32_t so = sbase + st*STAGE_BYTES;
        int ko = kt*BKt;
        #pragma unroll
        for (int i = 0; i < CPR; ++i) cp16(so + oA[i], Ag[i] + ko);
        #pragma unroll
        for (int i = 0; i < CPR; ++i) cp16(so + oB[i], Bg[i] + ko);
        asm volatile("cp.async.commit_group;\n");
    };

    auto compute = [&](int st) {
        uint32_t abase = sbase + st*STAGE_BYTES;
        uint32_t bbase = abase + A_BYTES;
        #pragma unroll
        for (int ks = 0; ks < KS; ++ks) {
            uint32_t a[4][4], bb[8][2];
            #pragma unroll
            for (int mt = 0; mt < 4; ++mt) {
                int rr = arow[mt];
                uint32_t ad = abase + rr*ROWB + swz(2*ks + akadd, rr)*16;
                asm volatile("ldmatrix.sync.aligned.m8n8.x4.shared.b16 {%0,%1,%2,%3},[%4];"
                    : "=r"(a[mt][0]), "=r"(a[mt][1]), "=r"(a[mt][2]), "=r"(a[mt][3]) : "r"(ad));
            }
            #pragma unroll
            for (int p = 0; p < 4; ++p) {
                int rr = brow[p];
                uint32_t bd = bbase + rr*ROWB + swz(2*ks + bkadd, rr)*16;
                asm volatile("ldmatrix.sync.aligned.m8n8.x4.shared.b16 {%0,%1,%2,%3},[%4];"
                    : "=r"(bb[2*p][0]), "=r"(bb[2*p][1]),
                      "=r"(bb[2*p+1][0]), "=r"(bb[2*p+1][1]) : "r"(bd));
            }
            #pragma unroll
            for (int mt = 0; mt < 4; ++mt)
                #pragma unroll
                for (int nt = 0; nt < 8; ++nt)
                    asm volatile(
                        "mma.sync.aligned.m16n8k16.row.col.f32.f16.f16.f32 "
                        "{%0,%1,%2,%3},{%4,%5,%6,%7},{%8,%9},{%0,%1,%2,%3};\n"
                        : "+f"(acc[mt][nt][0]), "+f"(acc[mt][nt][1]),
                          "+f"(acc[mt][nt][2]), "+f"(acc[mt][nt][3])
                        : "r"(a[mt][0]), "r"(a[mt][1]), "r"(a[mt][2]), "r"(a[mt][3]),
                          "r"(bb[nt][0]), "r"(bb[nt][1]));
        }
    };

    const int ntile = Kdim / BKt;
    #pragma unroll
    for (int p = 0; p < STGt - 1; ++p) issue(p, p);
    for (int t = 0; t < ntile; ++t) {
        int rem = ntile - 1 - t;
        if      (STGt >= 4 && rem >= 2) asm volatile("cp.async.wait_group 2;\n" ::: "memory");
        else if (STGt >= 3 && rem >= 1) asm volatile("cp.async.wait_group 1;\n" ::: "memory");
        else                            asm volatile("cp.async.wait_group 0;\n" ::: "memory");
        __syncthreads();
        compute(t % STGt);
        if (t + STGt - 1 < ntile) issue(t + STGt - 1, (t + STGt - 1) % STGt);
    }

    const int g = lane >> 2, q = lane & 3;

    if (FSTAT) {
        float sum[16], sq[16];
        #pragma unroll
        for (int i = 0; i < 16; ++i) { sum[i] = 0.f; sq[i] = 0.f; }
        #pragma unroll
        for (int mt = 0; mt < 4; ++mt) {
            int rr = wm*64 + mt*16 + g;
            bool ok0 = (rr & 63) < K_;
            bool ok1 = ((rr + 8) & 63) < K_;
            #pragma unroll
            for (int nt = 0; nt < 8; ++nt) {
                int c = n0 + wn*64 + nt*8 + q*2;
                float b0 = bias[c], b1 = bias[c+1];
                float v00 = acc[mt][nt][0] + b0, v01 = acc[mt][nt][1] + b1;
                float v10 = acc[mt][nt][2] + b0, v11 = acc[mt][nt][3] + b1;
                int r = m0 + rr;
                if (ok0) {
                    *(__half2*)&Ch[(size_t)r*ldc + c] = __floats2half2_rn(v00, v01);
                    sum[nt*2]   += v00; sq[nt*2]   += v00*v00;
                    sum[nt*2+1] += v01; sq[nt*2+1] += v01*v01;
                }
                if (ok1) {
                    *(__half2*)&Ch[(size_t)(r+8)*ldc + c] = __floats2half2_rn(v10, v11);
                    sum[nt*2]   += v10; sq[nt*2]   += v10*v10;
                    sum[nt*2+1] += v11; sq[nt*2+1] += v11*v11;
                }
            }
        }
        #pragma unroll
        for (int off = 4; off < 32; off <<= 1) {
            #pragma unroll
            for (int i = 0; i < 16; ++i) {
                sum[i] += __shfl_xor_sync(0xffffffffu, sum[i], off);
                sq[i]  += __shfl_xor_sync(0xffffffffu, sq[i],  off);
            }
        }
        if (lane < 4) {
            #pragma unroll
            for (int nt = 0; nt < 8; ++nt) {
                #pragma unroll
                for (int j = 0; j < 2; ++j) {
                    int c = n0 + wn*64 + nt*8 + lane*2 + j;
                    atomicAdd(&stats[c],      sum[nt*2+j]);
                    atomicAdd(&stats[H_ + c], sq[nt*2+j]);
                }
            }
        }
    } else {
        float mx[16];
        #pragma unroll
        for (int i = 0; i < 16; ++i) mx[i] = -3.4e38f;
        #pragma unroll
        for (int mt = 0; mt < 4; ++mt) {
            int k0 = mt*16 + g;
            bool ok0 = k0 < K_, ok1 = (k0 + 8) < K_;
            #pragma unroll
            for (int nt = 0; nt < 8; ++nt) {
                int c = n0 + wn*64 + nt*8 + q*2;
                float b0 = bias[c], b1 = bias[c+1];
                if (ok0) { mx[nt*2]   = fmaxf(mx[nt*2],   acc[mt][nt][0] + b0);
                           mx[nt*2+1] = fmaxf(mx[nt*2+1], acc[mt][nt][1] + b1); }
                if (ok1) { mx[nt*2]   = fmaxf(mx[nt*2],   acc[mt][nt][2] + b0);
                           mx[nt*2+1] = fmaxf(mx[nt*2+1], acc[mt][nt][3] + b1); }
            }
        }
        #pragma unroll
        for (int off = 4; off < 32; off <<= 1)
            #pragma unroll
            for (int i = 0; i < 16; ++i)
                mx[i] = fmaxf(mx[i], __shfl_xor_sync(0xffffffffu, mx[i], off));
        if (lane < 4) {
            int b = blockIdx.y*2 + wm;
            #pragma unroll
            for (int nt = 0; nt < 8; ++nt) {
                int c = n0 + wn*64 + nt*8 + lane*2;
                *(float2*)&omax[(size_t)b*E_ + c] = make_float2(mx[nt*2], mx[nt*2+1]);
            }
        }
    }
}

// ---------------- BN apply + ReLU + fp16 into X[:,512:] (fused params) --------
// Each block computes all 512 scale/shift pairs in smem (2 rsqrt/thread),
// then streams 8 halfs per thread (uint4 in/out).
__global__ void bnapply_kernel(const float* __restrict__ gamma, const float* __restrict__ beta)
{
    __shared__ float ssc[H_], ssh[H_];
    int t = threadIdx.x;
    const float invM = 1.f / (float)M_;
    #pragma unroll
    for (int j = 0; j < 2; ++j) {
        int c = t + j*256;
        float mu  = g_stats[c] * invM;
        float var = g_stats[H_ + c] * invM - mu*mu;
        float sc  = rsqrtf(var + 1e-5f) * gamma[c];
        ssc[c] = sc;
        ssh[c] = beta[c] - mu*sc;
    }
    __syncthreads();
    int i = blockIdx.x*256 + t;              // 0 .. M_*H_/8 - 1
    int row = i >> 6;                        // real row (64 threads/row)
    int c8  = (i & 63)*8;                    // col start (multiple of 8)
    int b = row / K_;
    int k = row - b*K_;
    size_t r = (size_t)(b*64 + k);
    uint4 xv = *(const uint4*)&g_hpre[r*H_ + c8];
    float4 sc0 = *(const float4*)&ssc[c8];
    float4 sc1 = *(const float4*)&ssc[c8 + 4];
    float4 sh0 = *(const float4*)&ssh[c8];
    float4 sh1 = *(const float4*)&ssh[c8 + 4];
    const __half2* xh = (const __half2*)&xv;
    __half2 yv[4];
    {
        float2 x = __half22float2(xh[0]);
        yv[0] = __floats2half2_rn(fmaxf(x.x*sc0.x + sh0.x, 0.f), fmaxf(x.y*sc0.y + sh0.y, 0.f));
    }
    {
        float2 x = __half22float2(xh[1]);
        yv[1] = __floats2half2_rn(fmaxf(x.x*sc0.z + sh0.z, 0.f), fmaxf(x.y*sc0.w + sh0.w, 0.f));
    }
    {
        float2 x = __half22float2(xh[2]);
        yv[2] = __floats2half2_rn(fmaxf(x.x*sc1.x + sh1.x, 0.f), fmaxf(x.y*sc1.y + sh1.y, 0.f));
    }
    {
        float2 x = __half22float2(xh[3]);
        yv[3] = __floats2half2_rn(fmaxf(x.x*sc1.z + sh1.z, 0.f), fmaxf(x.y*sc1.w + sh1.w, 0.f));
    }
    *(uint4*)&g_X[r*1024 + 512 + c8] = *(const uint4*)yv;
}

// ---------------- launch ------------------------------------------------------
extern "C" void kernel_launch(void* const* d_in, const int* in_sizes, int n_in,
                              void* d_out, int out_size)
{
    const float* emb   = (const float*)d_in[0];
    const float* am    = (const float*)d_in[1];
    const float* Wfc   = (const float*)d_in[2];
    const float* bfc   = (const float*)d_in[3];
    const float* W1    = (const float*)d_in[4];
    const float* b1    = (const float*)d_in[5];
    const float* gamma = (const float*)d_in[6];
    const float* beta  = (const float*)d_in[7];
    const float* W2    = (const float*)d_in[8];
    const float* b2    = (const float*)d_in[9];
    float* out = (float*)d_out;

    void *pX, *pW1h, *pWcat, *pH, *pB2, *pSt;
    cudaGetSymbolAddress(&pX,    g_X);
    cudaGetSymbolAddress(&pW1h,  g_W1h);
    cudaGetSymbolAddress(&pWcat, g_Wcat);
    cudaGetSymbolAddress(&pH,    g_hpre);
    cudaGetSymbolAddress(&pB2,   g_bias2);
    cudaGetSymbolAddress(&pSt,   g_stats);

    const int SMEM1 = 4*(BMt + BN)*32*2;   // 65536  (BK=32, 4-stage, 3 CTAs/SM)
    const int SMEM2 = 3*(BMt + BN)*64*2;   // 98304  (BK=64, 3-stage, 2 CTAs/SM)
    cudaFuncSetAttribute((const void*)gemm_tc<true, 32, 4, 3>,
                         cudaFuncAttributeMaxDynamicSharedMemorySize, SMEM1);
    cudaFuncSetAttribute((const void*)gemm_tc<false, 64, 3, 2>,
                         cudaFuncAttributeMaxDynamicSharedMemorySize, SMEM2);

    // fused: topk+gather (blocks 0..B*N-1) + weight prep (next 8192 blocks)
    gather_topk_kernel<<<B_*N_ + 8192, 128>>>(emb, am, Wfc, bfc, W1, W2, b2);
    // GEMM1: hpre(fp16) = base @ W1^T + b1, fused BN stats
    gemm_tc<true, 32, 4, 3><<<dim3(H_/BN, MP_/BMt), 128, SMEM1>>>(
        (const __half*)pX, 1024, (const __half*)pW1h, D_,
        (__half*)pH, H_, b1, D_, (float*)pSt, nullptr);
    // BN params (in-block) + apply + ReLU + fp16
    bnapply_kernel<<<(M_*H_/8)/256, 256>>>(gamma, beta);
    // GEMM2: out[b,:] = max_k( X @ [Wfc|W2]^T + (b_fc+b2) )
    gemm_tc<false, 64, 3, 2><<<dim3(E_/BN, MP_/BMt), 128, SMEM2>>>(
        (const __half*)pX, 1024, (const __half*)pWcat, 1024,
        nullptr, 0, (const float*)pB2, 1024, nullptr, out);
}

// round 16
// speedup vs baseline: 1.1193x; 1.1193x over previous
#include <cuda_runtime.h>
#include <cuda_fp16.h>
#include <cstdint>

#define B_ 256
#define N_ 192
#define D_ 512
#define E_ 1024
#define H_ 512
#define K_ 58
#define M_ (B_*K_)        // 14848 real rows
#define MP_ (B_*64)       // 16384 padded rows (64 per batch, rows k>=58 stay zero)

// ---------------- scratch (static device globals; zero-init, no allocation) --
__device__ __half g_X[(size_t)MP_*1024];    // [MP,1024]: 0:512 base, 512:1024 bn(relu(h)); pad rows 0
__device__ __half g_hpre[(size_t)MP_*H_];   // [MP,512] fp16 pre-BN hidden
__device__ __half g_W1h[H_*D_];             // fp16 W1
__device__ __half g_Wcat[E_*1024];          // fp16 [W_fc | W2]
__device__ float  g_bias2[E_];              // b_fc + b2
__device__ float  g_stats[2*H_];            // col sums / sumsq
__device__ int    g_idx[B_*K_];             // selected patch indices

// ---------------- top-K by rank counting (exact lax.top_k set semantics) -----
__global__ void topk_kernel(const float* __restrict__ am)
{
    __shared__ float sv[N_];
    __shared__ int cnt;
    int b = blockIdx.x, t = threadIdx.x;
    if (t == 0) cnt = 0;
    sv[t] = am[(size_t)b*((N_+1)*(N_+1)) + 1 + t];
    __syncthreads();
    float my = sv[t];
    int r = 0;
    #pragma unroll 8
    for (int i = 0; i < N_; ++i) {
        float v = sv[i];
        r += (v > my) || (v == my && i < t);
    }
    if (r < K_) {
        int p = atomicAdd(&cnt, 1);
        g_idx[b*K_ + p] = t;
    }
}

// ---------------- fused prep + gather (disjoint block ranges, one launch) -----
__global__ void prep_gather_kernel(const float* __restrict__ emb,
                                   const float* __restrict__ Wfc, const float* __restrict__ bfc,
                                   const float* __restrict__ W1,  const float* __restrict__ W2,
                                   const float* __restrict__ b2)
{
    int bid = blockIdx.x;
    int t = threadIdx.x;
    if (bid < M_) {
        int b   = bid / K_;
        int k   = bid - b*K_;
        int p   = g_idx[bid];
        const float4* src = (const float4*)(emb + (size_t)(b*N_ + p)*D_);
        float4 v = src[t];
        float s = v.x*v.x + v.y*v.y + v.z*v.z + v.w*v.w;
        #pragma unroll
        for (int o = 16; o; o >>= 1) s += __shfl_xor_sync(0xffffffffu, s, o);
        __shared__ float sm[4];
        if ((t & 31) == 0) sm[t >> 5] = s;
        __syncthreads();
        float nrm = sqrtf(sm[0] + sm[1] + sm[2] + sm[3]) + 1e-8f;
        size_t r = (size_t)(b*64 + k);
        __half2* dst = (__half2*)(g_X + r*1024 + t*4);
        dst[0] = __floats2half2_rn(v.x/nrm, v.y/nrm);
        dst[1] = __floats2half2_rn(v.z/nrm, v.w/nrm);
    } else {
        int i = (bid - M_)*128 + t;        // 0..1048575
        {
            int e = i >> 10, c = i & 1023;
            float v = (c < 512) ? Wfc[e*512 + c] : W2[e*512 + (c - 512)];
            g_Wcat[i] = __float2half_rn(v);
        }
        if (i < H_*D_) g_W1h[i] = __float2half_rn(W1[i]);
        if (i < E_)    g_bias2[i] = bfc[i] + b2[i];
        if (i < 2*H_)  g_stats[i] = 0.f;
    }
}

// ---------------- fp16 tensor-core GEMM: C = A @ B^T + bias -------------------
// BM=128, BN=128; 128 threads = 4 warps (2x2), warp tile 64x64.
// GEMM1: BKt=32, STGt=4, MINB=3 -> 64KB smem, 3 CTAs/SM.
// GEMM2: BKt=64, STGt=3, MINB=2 -> 96KB smem, 2 CTAs/SM (R7 optimum, tensor 71%).
#define BMt 128
#define BN 128

__device__ __forceinline__ void cp16(uint32_t dst, const void* src) {
    asm volatile("cp.async.cg.shared.global [%0], [%1], 16;\n" :: "r"(dst), "l"(src));
}
__device__ __forceinline__ uint32_t smem_u32(const void* p) {
    uint32_t a;
    asm("{ .reg .u64 t; cvta.to.shared.u64 t, %1; cvt.u32.u64 %0, t; }" : "=r"(a) : "l"(p));
    return a;
}

template<bool FSTAT, int BKt, int STGt, int MINB>
__global__ __launch_bounds__(128, MINB)
void gemm_tc(const __half* __restrict__ A, int lda,
             const __half* __restrict__ Bm, int ldb,
             __half* __restrict__ Ch, int ldc,
             const float* __restrict__ bias, int Kdim,
             float* __restrict__ stats, float* __restrict__ omax)
{
    constexpr int STAGE_BYTES = (BMt + BN)*BKt*2;
    constexpr int A_BYTES     = BMt*BKt*2;
    constexpr int ROWB        = BKt*2;
    constexpr int CPR         = BKt/8;
    constexpr int RSTEP       = 128/CPR;
    constexpr int KS          = BKt/16;

    extern __shared__ __half sh[];
    const int tid  = threadIdx.x;
    const int lane = tid & 31, wid = tid >> 5;
    const int wm = wid >> 1, wn = wid & 1;
    const int m0 = blockIdx.y*BMt, n0 = blockIdx.x*BN;

    uint32_t sbase = smem_u32(sh);

    auto swz = [](int c, int r) -> int {
        return (BKt == 64) ? (c ^ (r & 7)) : (c ^ ((r >> 1) & 3));
    };

    float acc[4][8][4];
    #pragma unroll
    for (int i = 0; i < 4; ++i)
        #pragma unroll
        for (int j = 0; j < 8; ++j)
            #pragma unroll
            for (int k = 0; k < 4; ++k) acc[i][j][k] = 0.f;

    const int cr = tid / CPR;
    const int cc = tid % CPR;
    const __half* Ag[CPR]; uint32_t oA[CPR];
    #pragma unroll
    for (int i = 0; i < CPR; ++i) {
        int r = cr + i*RSTEP;
        Ag[i] = A + (size_t)(m0 + r)*lda + cc*8;
        oA[i] = r*ROWB + swz(cc, r)*16;
    }
    const __half* Bg[CPR]; uint32_t oB[CPR];
    #pragma unroll
    for (int i = 0; i < CPR; ++i) {
        int r = cr + i*RSTEP;
        Bg[i] = Bm + (size_t)(n0 + r)*ldb + cc*8;
        oB[i] = A_BYTES + r*ROWB + swz(cc, r)*16;
    }

    const int mi  = lane >> 3;
    const int lr8 = lane & 7;
    int arow[4];
    #pragma unroll
    for (int mt = 0; mt < 4; ++mt) arow[mt] = wm*64 + mt*16 + ((mi & 1) << 3) + lr8;
    const int akadd = mi >> 1;
    int brow[4];
    #pragma unroll
    for (int p = 0; p < 4; ++p) brow[p] = wn*64 + ((2*p + (mi >> 1)) << 3) + lr8;
    const int bkadd = mi & 1;

    auto issue = [&](int kt, int st) {
        uint32_t so = sbase + st*STAGE_BYTES;
        int ko = kt*BKt;
        #pragma unroll
        for (int i = 0; i < CPR; ++i) cp16(so + oA[i], Ag[i] + ko);
        #pragma unroll
        for (int i = 0; i < CPR; ++i) cp16(so + oB[i], Bg[i] + ko);
        asm volatile("cp.async.commit_group;\n");
    };

    auto compute = [&](int st) {
        uint32_t abase = sbase + st*STAGE_BYTES;
        uint32_t bbase = abase + A_BYTES;
        #pragma unroll
        for (int ks = 0; ks < KS; ++ks) {
            uint32_t a[4][4], bb[8][2];
            #pragma unroll
            for (int mt = 0; mt < 4; ++mt) {
                int rr = arow[mt];
                uint32_t ad = abase + rr*ROWB + swz(2*ks + akadd, rr)*16;
                asm volatile("ldmatrix.sync.aligned.m8n8.x4.shared.b16 {%0,%1,%2,%3},[%4];"
                    : "=r"(a[mt][0]), "=r"(a[mt][1]), "=r"(a[mt][2]), "=r"(a[mt][3]) : "r"(ad));
            }
            #pragma unroll
            for (int p = 0; p < 4; ++p) {
                int rr = brow[p];
                uint32_t bd = bbase + rr*ROWB + swz(2*ks + bkadd, rr)*16;
                asm volatile("ldmatrix.sync.aligned.m8n8.x4.shared.b16 {%0,%1,%2,%3},[%4];"
                    : "=r"(bb[2*p][0]), "=r"(bb[2*p][1]),
                      "=r"(bb[2*p+1][0]), "=r"(bb[2*p+1][1]) : "r"(bd));
            }
            #pragma unroll
            for (int mt = 0; mt < 4; ++mt)
                #pragma unroll
                for (int nt = 0; nt < 8; ++nt)
                    asm volatile(
                        "mma.sync.aligned.m16n8k16.row.col.f32.f16.f16.f32 "
                        "{%0,%1,%2,%3},{%4,%5,%6,%7},{%8,%9},{%0,%1,%2,%3};\n"
                        : "+f"(acc[mt][nt][0]), "+f"(acc[mt][nt][1]),
                          "+f"(acc[mt][nt][2]), "+f"(acc[mt][nt][3])
                        : "r"(a[mt][0]), "r"(a[mt][1]), "r"(a[mt][2]), "r"(a[mt][3]),
                          "r"(bb[nt][0]), "r"(bb[nt][1]));
        }
    };

    const int ntile = Kdim / BKt;
    #pragma unroll
    for (int p = 0; p < STGt - 1; ++p) issue(p, p);
    for (int t = 0; t < ntile; ++t) {
        int rem = ntile - 1 - t;
        if      (STGt >= 4 && rem >= 2) asm volatile("cp.async.wait_group 2;\n" ::: "memory");
        else if (STGt >= 3 && rem >= 1) asm volatile("cp.async.wait_group 1;\n" ::: "memory");
        else                            asm volatile("cp.async.wait_group 0;\n" ::: "memory");
        __syncthreads();
        compute(t % STGt);
        if (t + STGt - 1 < ntile) issue(t + STGt - 1, (t + STGt - 1) % STGt);
    }

    const int g = lane >> 2, q = lane & 3;

    if (FSTAT) {
        float sum[16], sq[16];
        #pragma unroll
        for (int i = 0; i < 16; ++i) { sum[i] = 0.f; sq[i] = 0.f; }
        #pragma unroll
        for (int mt = 0; mt < 4; ++mt) {
            int rr = wm*64 + mt*16 + g;
            bool ok0 = (rr & 63) < K_;
            bool ok1 = ((rr + 8) & 63) < K_;
            #pragma unroll
            for (int nt = 0; nt < 8; ++nt) {
                int c = n0 + wn*64 + nt*8 + q*2;
                float b0 = bias[c], b1 = bias[c+1];
                float v00 = acc[mt][nt][0] + b0, v01 = acc[mt][nt][1] + b1;
                float v10 = acc[mt][nt][2] + b0, v11 = acc[mt][nt][3] + b1;
                int r = m0 + rr;
                if (ok0) {
                    *(__half2*)&Ch[(size_t)r*ldc + c] = __floats2half2_rn(v00, v01);
                    sum[nt*2]   += v00; sq[nt*2]   += v00*v00;
                    sum[nt*2+1] += v01; sq[nt*2+1] += v01*v01;
                }
                if (ok1) {
                    *(__half2*)&Ch[(size_t)(r+8)*ldc + c] = __floats2half2_rn(v10, v11);
                    sum[nt*2]   += v10; sq[nt*2]   += v10*v10;
                    sum[nt*2+1] += v11; sq[nt*2+1] += v11*v11;
                }
            }
        }
        #pragma unroll
        for (int off = 4; off < 32; off <<= 1) {
            #pragma unroll
            for (int i = 0; i < 16; ++i) {
                sum[i] += __shfl_xor_sync(0xffffffffu, sum[i], off);
                sq[i]  += __shfl_xor_sync(0xffffffffu, sq[i],  off);
            }
        }
        if (lane < 4) {
            #pragma unroll
            for (int nt = 0; nt < 8; ++nt) {
                #pragma unroll
                for (int j = 0; j < 2; ++j) {
                    int c = n0 + wn*64 + nt*8 + lane*2 + j;
                    atomicAdd(&stats[c],      sum[nt*2+j]);
                    atomicAdd(&stats[H_ + c], sq[nt*2+j]);
                }
            }
        }
    } else {
        float mx[16];
        #pragma unroll
        for (int i = 0; i < 16; ++i) mx[i] = -3.4e38f;
        #pragma unroll
        for (int mt = 0; mt < 4; ++mt) {
            int k0 = mt*16 + g;
            bool ok0 = k0 < K_, ok1 = (k0 + 8) < K_;
            #pragma unroll
            for (int nt = 0; nt < 8; ++nt) {
                int c = n0 + wn*64 + nt*8 + q*2;
                float b0 = bias[c], b1 = bias[c+1];
                if (ok0) { mx[nt*2]   = fmaxf(mx[nt*2],   acc[mt][nt][0] + b0);
                           mx[nt*2+1] = fmaxf(mx[nt*2+1], acc[mt][nt][1] + b1); }
                if (ok1) { mx[nt*2]   = fmaxf(mx[nt*2],   acc[mt][nt][2] + b0);
                           mx[nt*2+1] = fmaxf(mx[nt*2+1], acc[mt][nt][3] + b1); }
            }
        }
        #pragma unroll
        for (int off = 4; off < 32; off <<= 1)
            #pragma unroll
            for (int i = 0; i < 16; ++i)
                mx[i] = fmaxf(mx[i], __shfl_xor_sync(0xffffffffu, mx[i], off));
        if (lane < 4) {
            int b = blockIdx.y*2 + wm;
            #pragma unroll
            for (int nt = 0; nt < 8; ++nt) {
                int c = n0 + wn*64 + nt*8 + lane*2;
                *(float2*)&omax[(size_t)b*E_ + c] = make_float2(mx[nt*2], mx[nt*2+1]);
            }
        }
    }
}

// ---------------- BN apply + ReLU + fp16 into X[:,512:] (fused params) --------
// Each block computes all 512 scale/shift pairs in smem (2 rsqrt/thread),
// then streams 8 halfs per thread (uint4 in/out).
__global__ void bnapply_kernel(const float* __restrict__ gamma, const float* __restrict__ beta)
{
    __shared__ float ssc[H_], ssh[H_];
    int t = threadIdx.x;
    const float invM = 1.f / (float)M_;
    #pragma unroll
    for (int j = 0; j < 2; ++j) {
        int c = t + j*256;
        float mu  = g_stats[c] * invM;
        float var = g_stats[H_ + c] * invM - mu*mu;
        float sc  = rsqrtf(var + 1e-5f) * gamma[c];
        ssc[c] = sc;
        ssh[c] = beta[c] - mu*sc;
    }
    __syncthreads();
    int i = blockIdx.x*256 + t;              // 0 .. M_*H_/8 - 1
    int row = i >> 6;                        // real row (64 threads/row)
    int c8  = (i & 63)*8;                    // col start (multiple of 8)
    int b = row / K_;
    int k = row - b*K_;
    size_t r = (size_t)(b*64 + k);
    uint4 xv = *(const uint4*)&g_hpre[r*H_ + c8];
    float4 sc0 = *(const float4*)&ssc[c8];
    float4 sc1 = *(const float4*)&ssc[c8 + 4];
    float4 sh0 = *(const float4*)&ssh[c8];
    float4 sh1 = *(const float4*)&ssh[c8 + 4];
    const __half2* xh = (const __half2*)&xv;
    __half2 yv[4];
    {
        float2 x = __half22float2(xh[0]);
        yv[0] = __floats2half2_rn(fmaxf(x.x*sc0.x + sh0.x, 0.f), fmaxf(x.y*sc0.y + sh0.y, 0.f));
    }
    {
        float2 x = __half22float2(xh[1]);
        yv[1] = __floats2half2_rn(fmaxf(x.x*sc0.z + sh0.z, 0.f), fmaxf(x.y*sc0.w + sh0.w, 0.f));
    }
    {
        float2 x = __half22float2(xh[2]);
        yv[2] = __floats2half2_rn(fmaxf(x.x*sc1.x + sh1.x, 0.f), fmaxf(x.y*sc1.y + sh1.y, 0.f));
    }
    {
        float2 x = __half22float2(xh[3]);
        yv[3] = __floats2half2_rn(fmaxf(x.x*sc1.z + sh1.z, 0.f), fmaxf(x.y*sc1.w + sh1.w, 0.f));
    }
    *(uint4*)&g_X[r*1024 + 512 + c8] = *(const uint4*)yv;
}

// ---------------- launch ------------------------------------------------------
extern "C" void kernel_launch(void* const* d_in, const int* in_sizes, int n_in,
                              void* d_out, int out_size)
{
    const float* emb   = (const float*)d_in[0];
    const float* am    = (const float*)d_in[1];
    const float* Wfc   = (const float*)d_in[2];
    const float* bfc   = (const float*)d_in[3];
    const float* W1    = (const float*)d_in[4];
    const float* b1    = (const float*)d_in[5];
    const float* gamma = (const float*)d_in[6];
    const float* beta  = (const float*)d_in[7];
    const float* W2    = (const float*)d_in[8];
    const float* b2    = (const float*)d_in[9];
    float* out = (float*)d_out;

    void *pX, *pW1h, *pWcat, *pH, *pB2, *pSt;
    cudaGetSymbolAddress(&pX,    g_X);
    cudaGetSymbolAddress(&pW1h,  g_W1h);
    cudaGetSymbolAddress(&pWcat, g_Wcat);
    cudaGetSymbolAddress(&pH,    g_hpre);
    cudaGetSymbolAddress(&pB2,   g_bias2);
    cudaGetSymbolAddress(&pSt,   g_stats);

    const int SMEM1 = 4*(BMt + BN)*32*2;   // 65536  (BK=32, 4-stage, 3 CTAs/SM)
    const int SMEM2 = 3*(BMt + BN)*64*2;   // 98304  (BK=64, 3-stage, 2 CTAs/SM)
    cudaFuncSetAttribute((const void*)gemm_tc<true, 32, 4, 3>,
                         cudaFuncAttributeMaxDynamicSharedMemorySize, SMEM1);
    cudaFuncSetAttribute((const void*)gemm_tc<false, 64, 3, 2>,
                         cudaFuncAttributeMaxDynamicSharedMemorySize, SMEM2);

    topk_kernel<<<B_, N_>>>(am);
    prep_gather_kernel<<<M_ + 8192, 128>>>(emb, Wfc, bfc, W1, W2, b2);
    // GEMM1: hpre(fp16) = base @ W1^T + b1, fused BN stats
    gemm_tc<true, 32, 4, 3><<<dim3(H_/BN, MP_/BMt), 128, SMEM1>>>(
        (const __half*)pX, 1024, (const __half*)pW1h, D_,
        (__half*)pH, H_, b1, D_, (float*)pSt, nullptr);
    // BN params (in-block) + apply + ReLU + fp16
    bnapply_kernel<<<(M_*H_/8)/256, 256>>>(gamma, beta);
    // GEMM2: out[b,:] = max_k( X @ [Wfc|W2]^T + (b_fc+b2) )
    gemm_tc<false, 64, 3, 2><<<dim3(E_/BN, MP_/BMt), 128, SMEM2>>>(
        (const __half*)pX, 1024, (const __half*)pWcat, 1024,
        nullptr, 0, (const float*)pB2, 1024, nullptr, out);
}

// round 17
// speedup vs baseline: 1.1341x; 1.0132x over previous
#include <cuda_runtime.h>
#include <cuda_fp16.h>
#include <cstdint>

#define B_ 256
#define N_ 192
#define D_ 512
#define E_ 1024
#define H_ 512
#define K_ 58
#define M_ (B_*K_)        // 14848 real rows
#define MP_ (B_*64)       // 16384 padded rows (64 per batch, rows k>=58 stay zero)

// ---------------- scratch (static device globals; zero-init, no allocation) --
__device__ __half g_X[(size_t)MP_*1024];    // [MP,1024]: 0:512 base, 512:1024 bn(relu(h)); pad rows 0
__device__ __half g_hpre[(size_t)MP_*H_];   // [MP,512] fp16 pre-BN hidden
__device__ __half g_W1h[H_*D_];             // fp16 W1
__device__ __half g_Wcat[E_*1024];          // fp16 [W_fc | W2]
__device__ float  g_bias2[E_];              // b_fc + b2
__device__ float  g_stats[2*H_];            // col sums / sumsq
__device__ int    g_idx[B_*K_];             // selected patch indices

// ---------------- top-K by rank counting (exact lax.top_k set semantics) -----
__global__ void topk_kernel(const float* __restrict__ am)
{
    __shared__ float sv[N_];
    __shared__ int cnt;
    int b = blockIdx.x, t = threadIdx.x;
    if (t == 0) cnt = 0;
    sv[t] = am[(size_t)b*((N_+1)*(N_+1)) + 1 + t];
    __syncthreads();
    float my = sv[t];
    int r = 0;
    #pragma unroll 8
    for (int i = 0; i < N_; ++i) {
        float v = sv[i];
        r += (v > my) || (v == my && i < t);
    }
    if (r < K_) {
        int p = atomicAdd(&cnt, 1);
        g_idx[b*K_ + p] = t;
    }
}

// ---------------- fused prep + gather (disjoint block ranges, one launch) -----
__global__ void prep_gather_kernel(const float* __restrict__ emb,
                                   const float* __restrict__ Wfc, const float* __restrict__ bfc,
                                   const float* __restrict__ W1,  const float* __restrict__ W2,
                                   const float* __restrict__ b2)
{
    int bid = blockIdx.x;
    int t = threadIdx.x;
    if (bid < M_) {
        int b   = bid / K_;
        int k   = bid - b*K_;
        int p   = g_idx[bid];
        const float4* src = (const float4*)(emb + (size_t)(b*N_ + p)*D_);
        float4 v = src[t];
        float s = v.x*v.x + v.y*v.y + v.z*v.z + v.w*v.w;
        #pragma unroll
        for (int o = 16; o; o >>= 1) s += __shfl_xor_sync(0xffffffffu, s, o);
        __shared__ float sm[4];
        if ((t & 31) == 0) sm[t >> 5] = s;
        __syncthreads();
        float nrm = sqrtf(sm[0] + sm[1] + sm[2] + sm[3]) + 1e-8f;
        size_t r = (size_t)(b*64 + k);
        __half2* dst = (__half2*)(g_X + r*1024 + t*4);
        dst[0] = __floats2half2_rn(v.x/nrm, v.y/nrm);
        dst[1] = __floats2half2_rn(v.z/nrm, v.w/nrm);
    } else {
        int i = (bid - M_)*128 + t;        // 0..1048575
        {
            int e = i >> 10, c = i & 1023;
            float v = (c < 512) ? Wfc[e*512 + c] : W2[e*512 + (c - 512)];
            g_Wcat[i] = __float2half_rn(v);
        }
        if (i < H_*D_) g_W1h[i] = __float2half_rn(W1[i]);
        if (i < E_)    g_bias2[i] = bfc[i] + b2[i];
        if (i < 2*H_)  g_stats[i] = 0.f;
    }
}

// ---------------- fp16 tensor-core GEMM: C = A @ B^T + bias -------------------
// BM=128, BN=128; 128 threads = 4 warps (2x2), warp tile 64x64.
// GEMM1: BKt=32, STGt=4, MINB=3 -> 64KB smem, 3 CTAs/SM.
// GEMM2: BKt=64, STGt=3, MINB=2 -> 96KB smem, 2 CTAs/SM (tensor 71%).
#define BMt 128
#define BN 128

__device__ __forceinline__ void cp16(uint32_t dst, const void* src) {
    asm volatile("cp.async.cg.shared.global [%0], [%1], 16;\n" :: "r"(dst), "l"(src));
}
__device__ __forceinline__ uint32_t smem_u32(const void* p) {
    uint32_t a;
    asm("{ .reg .u64 t; cvta.to.shared.u64 t, %1; cvt.u32.u64 %0, t; }" : "=r"(a) : "l"(p));
    return a;
}

template<bool FSTAT, int BKt, int STGt, int MINB>
__global__ __launch_bounds__(128, MINB)
void gemm_tc(const __half* __restrict__ A, int lda,
             const __half* __restrict__ Bm, int ldb,
             __half* __restrict__ Ch, int ldc,
             const float* __restrict__ bias, int Kdim,
             float* __restrict__ stats, float* __restrict__ omax)
{
    constexpr int STAGE_BYTES = (BMt + BN)*BKt*2;
    constexpr int A_BYTES     = BMt*BKt*2;
    constexpr int ROWB        = BKt*2;
    constexpr int CPR         = BKt/8;
    constexpr int RSTEP       = 128/CPR;
    constexpr int KS          = BKt/16;

    extern __shared__ __half sh[];
    const int tid  = threadIdx.x;
    const int lane = tid & 31, wid = tid >> 5;
    const int wm = wid >> 1, wn = wid & 1;
    const int m0 = blockIdx.y*BMt, n0 = blockIdx.x*BN;

    uint32_t sbase = smem_u32(sh);

    auto swz = [](int c, int r) -> int {
        return (BKt == 64) ? (c ^ (r & 7)) : (c ^ ((r >> 1) & 3));
    };

    float acc[4][8][4];
    #pragma unroll
    for (int i = 0; i < 4; ++i)
        #pragma unroll
        for (int j = 0; j < 8; ++j)
            #pragma unroll
            for (int k = 0; k < 4; ++k) acc[i][j][k] = 0.f;

    const int cr = tid / CPR;
    const int cc = tid % CPR;
    const __half* Ag[CPR]; uint32_t oA[CPR];
    #pragma unroll
    for (int i = 0; i < CPR; ++i) {
        int r = cr + i*RSTEP;
        Ag[i] = A + (size_t)(m0 + r)*lda + cc*8;
        oA[i] = r*ROWB + swz(cc, r)*16;
    }
    const __half* Bg[CPR]; uint32_t oB[CPR];
    #pragma unroll
    for (int i = 0; i < CPR; ++i) {
        int r = cr + i*RSTEP;
        Bg[i] = Bm + (size_t)(n0 + r)*ldb + cc*8;
        oB[i] = A_BYTES + r*ROWB + swz(cc, r)*16;
    }

    const int mi  = lane >> 3;
    const int lr8 = lane & 7;
    int arow[4];
    #pragma unroll
    for (int mt = 0; mt < 4; ++mt) arow[mt] = wm*64 + mt*16 + ((mi & 1) << 3) + lr8;
    const int akadd = mi >> 1;
    int brow[4];
    #pragma unroll
    for (int p = 0; p < 4; ++p) brow[p] = wn*64 + ((2*p + (mi >> 1)) << 3) + lr8;
    const int bkadd = mi & 1;

    auto issue = [&](int kt, int st) {
        uint32_t so = sbase + st*STAGE_BYTES;
        int ko = kt*BKt;
        #pragma unroll
        for (int i = 0; i < CPR; ++i) cp16(so + oA[i], Ag[i] + ko);
        #pragma unroll
        for (int i = 0; i < CPR; ++i) cp16(so + oB[i], Bg[i] + ko);
        asm volatile("cp.async.commit_group;\n");
    };

    auto compute = [&](int st) {
        uint32_t abase = sbase + st*STAGE_BYTES;
        uint32_t bbase = abase + A_BYTES;
        #pragma unroll
        for (int ks = 0; ks < KS; ++ks) {
            uint32_t a[4][4], bb[8][2];
            #pragma unroll
            for (int mt = 0; mt < 4; ++mt) {
                int rr = arow[mt];
                uint32_t ad = abase + rr*ROWB + swz(2*ks + akadd, rr)*16;
                asm volatile("ldmatrix.sync.aligned.m8n8.x4.shared.b16 {%0,%1,%2,%3},[%4];"
                    : "=r"(a[mt][0]), "=r"(a[mt][1]), "=r"(a[mt][2]), "=r"(a[mt][3]) : "r"(ad));
            }
            #pragma unroll
            for (int p = 0; p < 4; ++p) {
                int rr = brow[p];
                uint32_t bd = bbase + rr*ROWB + swz(2*ks + bkadd, rr)*16;
                asm volatile("ldmatrix.sync.aligned.m8n8.x4.shared.b16 {%0,%1,%2,%3},[%4];"
                    : "=r"(bb[2*p][0]), "=r"(bb[2*p][1]),
                      "=r"(bb[2*p+1][0]), "=r"(bb[2*p+1][1]) : "r"(bd));
            }
            #pragma unroll
            for (int mt = 0; mt < 4; ++mt)
                #pragma unroll
                for (int nt = 0; nt < 8; ++nt)
                    asm volatile(
                        "mma.sync.aligned.m16n8k16.row.col.f32.f16.f16.f32 "
                        "{%0,%1,%2,%3},{%4,%5,%6,%7},{%8,%9},{%0,%1,%2,%3};\n"
                        : "+f"(acc[mt][nt][0]), "+f"(acc[mt][nt][1]),
                          "+f"(acc[mt][nt][2]), "+f"(acc[mt][nt][3])
                        : "r"(a[mt][0]), "r"(a[mt][1]), "r"(a[mt][2]), "r"(a[mt][3]),
                          "r"(bb[nt][0]), "r"(bb[nt][1]));
        }
    };

    const int ntile = Kdim / BKt;
    #pragma unroll
    for (int p = 0; p < STGt - 1; ++p) issue(p, p);
    for (int t = 0; t < ntile; ++t) {
        int rem = ntile - 1 - t;
        if      (STGt >= 4 && rem >= 2) asm volatile("cp.async.wait_group 2;\n" ::: "memory");
        else if (STGt >= 3 && rem >= 1) asm volatile("cp.async.wait_group 1;\n" ::: "memory");
        else                            asm volatile("cp.async.wait_group 0;\n" ::: "memory");
        __syncthreads();
        compute(t % STGt);
        if (t + STGt - 1 < ntile) issue(t + STGt - 1, (t + STGt - 1) % STGt);
    }

    const int g = lane >> 2, q = lane & 3;

    if (FSTAT) {
        float sum[16], sq[16];
        #pragma unroll
        for (int i = 0; i < 16; ++i) { sum[i] = 0.f; sq[i] = 0.f; }
        #pragma unroll
        for (int mt = 0; mt < 4; ++mt) {
            int rr = wm*64 + mt*16 + g;
            bool ok0 = (rr & 63) < K_;
            bool ok1 = ((rr + 8) & 63) < K_;
            #pragma unroll
            for (int nt = 0; nt < 8; ++nt) {
                int c = n0 + wn*64 + nt*8 + q*2;
                float b0 = bias[c], b1 = bias[c+1];
                float v00 = acc[mt][nt][0] + b0, v01 = acc[mt][nt][1] + b1;
                float v10 = acc[mt][nt][2] + b0, v11 = acc[mt][nt][3] + b1;
                int r = m0 + rr;
                if (ok0) {
                    *(__half2*)&Ch[(size_t)r*ldc + c] = __floats2half2_rn(v00, v01);
                    sum[nt*2]   += v00; sq[nt*2]   += v00*v00;
                    sum[nt*2+1] += v01; sq[nt*2+1] += v01*v01;
                }
                if (ok1) {
                    *(__half2*)&Ch[(size_t)(r+8)*ldc + c] = __floats2half2_rn(v10, v11);
                    sum[nt*2]   += v10; sq[nt*2]   += v10*v10;
                    sum[nt*2+1] += v11; sq[nt*2+1] += v11*v11;
                }
            }
        }
        #pragma unroll
        for (int off = 4; off < 32; off <<= 1) {
            #pragma unroll
            for (int i = 0; i < 16; ++i) {
                sum[i] += __shfl_xor_sync(0xffffffffu, sum[i], off);
                sq[i]  += __shfl_xor_sync(0xffffffffu, sq[i],  off);
            }
        }
        if (lane < 4) {
            #pragma unroll
            for (int nt = 0; nt < 8; ++nt) {
                #pragma unroll
                for (int j = 0; j < 2; ++j) {
                    int c = n0 + wn*64 + nt*8 + lane*2 + j;
                    atomicAdd(&stats[c],      sum[nt*2+j]);
                    atomicAdd(&stats[H_ + c], sq[nt*2+j]);
                }
            }
        }
    } else {
        float mx[16];
        #pragma unroll
        for (int i = 0; i < 16; ++i) mx[i] = -3.4e38f;
        #pragma unroll
        for (int mt = 0; mt < 4; ++mt) {
            int k0 = mt*16 + g;
            bool ok0 = k0 < K_, ok1 = (k0 + 8) < K_;
            #pragma unroll
            for (int nt = 0; nt < 8; ++nt) {
                int c = n0 + wn*64 + nt*8 + q*2;
                float b0 = bias[c], b1 = bias[c+1];
                if (ok0) { mx[nt*2]   = fmaxf(mx[nt*2],   acc[mt][nt][0] + b0);
                           mx[nt*2+1] = fmaxf(mx[nt*2+1], acc[mt][nt][1] + b1); }
                if (ok1) { mx[nt*2]   = fmaxf(mx[nt*2],   acc[mt][nt][2] + b0);
                           mx[nt*2+1] = fmaxf(mx[nt*2+1], acc[mt][nt][3] + b1); }
            }
        }
        #pragma unroll
        for (int off = 4; off < 32; off <<= 1)
            #pragma unroll
            for (int i = 0; i < 16; ++i)
                mx[i] = fmaxf(mx[i], __shfl_xor_sync(0xffffffffu, mx[i], off));
        if (lane < 4) {
            int b = blockIdx.y*2 + wm;
            #pragma unroll
            for (int nt = 0; nt < 8; ++nt) {
                int c = n0 + wn*64 + nt*8 + lane*2;
                *(float2*)&omax[(size_t)b*E_ + c] = make_float2(mx[nt*2], mx[nt*2+1]);
            }
        }
    }
}

// ---------------- BN apply + ReLU + fp16 into X[:,512:] -----------------------
// Params packed as half2 tables (16B per 8 cols); each thread handles 2 rows x
// 8 cols, reusing params -> per row: 1 LDG.128 + 1 LDS.128 + 1 STG.128.
__global__ void bnapply_kernel(const float* __restrict__ gamma, const float* __restrict__ beta)
{
    __shared__ __align__(16) __half2 ssc2[H_/2];
    __shared__ __align__(16) __half2 ssh2[H_/2];
    int t = threadIdx.x;
    const float invM = 1.f / (float)M_;
    {
        int c0 = t*2, c1 = c0 + 1;
        float mu0 = g_stats[c0]*invM;
        float v0  = g_stats[H_ + c0]*invM - mu0*mu0;
        float s0  = rsqrtf(v0 + 1e-5f) * gamma[c0];
        float mu1 = g_stats[c1]*invM;
        float v1  = g_stats[H_ + c1]*invM - mu1*mu1;
        float s1  = rsqrtf(v1 + 1e-5f) * gamma[c1];
        ssc2[t] = __floats2half2_rn(s0, s1);
        ssh2[t] = __floats2half2_rn(beta[c0] - mu0*s0, beta[c1] - mu1*s1);
    }
    __syncthreads();
    int i  = blockIdx.x*256 + t;             // 0 .. M_*H_/16 - 1
    int rp = i >> 6;                         // row-pair index
    int c8 = (i & 63)*8;
    int row0 = rp*2, row1 = row0 + 1;
    int b0 = row0 / K_, k0 = row0 - b0*K_;
    int b1 = row1 / K_, k1 = row1 - b1*K_;
    size_t r0 = (size_t)(b0*64 + k0), r1 = (size_t)(b1*64 + k1);
    uint4 x0 = *(const uint4*)&g_hpre[r0*H_ + c8];
    uint4 x1 = *(const uint4*)&g_hpre[r1*H_ + c8];
    uint4 scv = *(const uint4*)&ssc2[c8 >> 1];
    uint4 shv = *(const uint4*)&ssh2[c8 >> 1];
    const __half2* sc = (const __half2*)&scv;
    const __half2* sha = (const __half2*)&shv;
    const __half2* xa = (const __half2*)&x0;
    const __half2* xb = (const __half2*)&x1;
    __half2 ya[4], yb[4];
    #pragma unroll
    for (int j = 0; j < 4; ++j) {
        float2 s = __half22float2(sc[j]);
        float2 h = __half22float2(sha[j]);
        float2 u = __half22float2(xa[j]);
        float2 v = __half22float2(xb[j]);
        ya[j] = __floats2half2_rn(fmaxf(u.x*s.x + h.x, 0.f), fmaxf(u.y*s.y + h.y, 0.f));
        yb[j] = __floats2half2_rn(fmaxf(v.x*s.x + h.x, 0.f), fmaxf(v.y*s.y + h.y, 0.f));
    }
    *(uint4*)&g_X[r0*1024 + 512 + c8] = *(const uint4*)ya;
    *(uint4*)&g_X[r1*1024 + 512 + c8] = *(const uint4*)yb;
}

// ---------------- launch ------------------------------------------------------
extern "C" void kernel_launch(void* const* d_in, const int* in_sizes, int n_in,
                              void* d_out, int out_size)
{
    const float* emb   = (const float*)d_in[0];
    const float* am    = (const float*)d_in[1];
    const float* Wfc   = (const float*)d_in[2];
    const float* bfc   = (const float*)d_in[3];
    const float* W1    = (const float*)d_in[4];
    const float* b1    = (const float*)d_in[5];
    const float* gamma = (const float*)d_in[6];
    const float* beta  = (const float*)d_in[7];
    const float* W2    = (const float*)d_in[8];
    const float* b2    = (const float*)d_in[9];
    float* out = (float*)d_out;

    void *pX, *pW1h, *pWcat, *pH, *pB2, *pSt;
    cudaGetSymbolAddress(&pX,    g_X);
    cudaGetSymbolAddress(&pW1h,  g_W1h);
    cudaGetSymbolAddress(&pWcat, g_Wcat);
    cudaGetSymbolAddress(&pH,    g_hpre);
    cudaGetSymbolAddress(&pB2,   g_bias2);
    cudaGetSymbolAddress(&pSt,   g_stats);

    const int SMEM1 = 4*(BMt + BN)*32*2;   // 65536  (BK=32, 4-stage, 3 CTAs/SM)
    const int SMEM2 = 3*(BMt + BN)*64*2;   // 98304  (BK=64, 3-stage, 2 CTAs/SM)
    cudaFuncSetAttribute((const void*)gemm_tc<true, 32, 4, 3>,
                         cudaFuncAttributeMaxDynamicSharedMemorySize, SMEM1);
    cudaFuncSetAttribute((const void*)gemm_tc<false, 64, 3, 2>,
                         cudaFuncAttributeMaxDynamicSharedMemorySize, SMEM2);

    topk_kernel<<<B_, N_>>>(am);
    prep_gather_kernel<<<M_ + 8192, 128>>>(emb, Wfc, bfc, W1, W2, b2);
    // GEMM1: hpre(fp16) = base @ W1^T + b1, fused BN stats
    gemm_tc<true, 32, 4, 3><<<dim3(H_/BN, MP_/BMt), 128, SMEM1>>>(
        (const __half*)pX, 1024, (const __half*)pW1h, D_,
        (__half*)pH, H_, b1, D_, (float*)pSt, nullptr);
    // BN params (in-block, half2-packed) + apply + ReLU + fp16
    bnapply_kernel<<<(M_*H_/16)/256, 256>>>(gamma, beta);
    // GEMM2: out[b,:] = max_k( X @ [Wfc|W2]^T + (b_fc+b2) )
    gemm_tc<false, 64, 3, 2><<<dim3(E_/BN, MP_/BMt), 128, SMEM2>>>(
        (const __half*)pX, 1024, (const __half*)pWcat, 1024,
        nullptr, 0, (const float*)pB2, 1024, nullptr, out);
}